// round 4
// baseline (speedup 1.0000x reference)
#include <cuda_runtime.h>

// out[b, p, d] = x[b, p] * W[p, d] + bias[p, d]
// B=64, P=2000, D=512 (fp32). HBM-write-bound: 262MB out (~6.6TB/s achieved).
//
// Persistent grid-stride: launch 148*8 = 1184 blocks (exactly one full
// residency set); each block iterates over virtual blocks, eliminating
// wave-quantization boundaries (previously 6.76 ragged waves). Each virtual
// block = 256 (p,d4) float4 columns x 8 batch rows. W/b/x are L2-resident;
// .cs streaming stores keep the 262MB output stream from evicting them.

#define B_DIM 64
#define P_DIM 2000
#define D_DIM 512
#define D4 (D_DIM / 4)              // 128
#define PD4 (P_DIM * D4)            // 256000
#define B_CHUNK 8                   // batches per virtual block
#define N_CHUNKS (B_DIM / B_CHUNK)  // 8
#define VBLOCKS_X (PD4 / 256)       // 1000 (exact)
#define N_VBLOCKS (VBLOCKS_X * N_CHUNKS)  // 8000
#define PERSISTENT_BLOCKS (148 * 8) // 1184

__global__ __launch_bounds__(256) void feature_expander_kernel(
    const float* __restrict__ x,      // [B, P]
    const float4* __restrict__ W,     // [P, D/4]
    const float4* __restrict__ bias,  // [P, D/4]
    float4* __restrict__ out)         // [B, P, D/4]
{
    int tid = threadIdx.x;

    for (int vb = blockIdx.x; vb < N_VBLOCKS; vb += gridDim.x) {
        int bx = vb % VBLOCKS_X;          // which 256-column strip
        int chunk = vb / VBLOCKS_X;       // which batch chunk
        int idx = bx * 256 + tid;         // (p, d4) flat index, always < PD4
        int p = idx >> 7;                 // idx / 128
        int b0 = chunk * B_CHUNK;

        float4 w = __ldg(&W[idx]);
        float4 bv = __ldg(&bias[idx]);

        const float* xp = x + b0 * P_DIM + p;
        float4* op = out + (size_t)b0 * PD4 + idx;

        #pragma unroll
        for (int i = 0; i < B_CHUNK; i++) {
            float xv = __ldg(xp + i * P_DIM);
            float4 o;
            o.x = fmaf(xv, w.x, bv.x);
            o.y = fmaf(xv, w.y, bv.y);
            o.z = fmaf(xv, w.z, bv.z);
            o.w = fmaf(xv, w.w, bv.w);
            __stcs(op + (size_t)i * PD4, o);   // streaming store
        }
    }
}

extern "C" void kernel_launch(void* const* d_in, const int* in_sizes, int n_in,
                              void* d_out, int out_size) {
    const float*  x  = (const float*)d_in[0];
    const float4* W  = (const float4*)d_in[1];
    const float4* bb = (const float4*)d_in[2];
    float4* out = (float4*)d_out;

    feature_expander_kernel<<<PERSISTENT_BLOCKS, 256>>>(x, W, bb, out);
}